// round 1
// baseline (speedup 1.0000x reference)
#include <cuda_runtime.h>
#include <cuda_bf16.h>
#include <cstdint>

// Problem constants
#define BATCH 128
#define NNODE 4096
#define DIM   32          // D_IN == D_OUT == 32
#define COLS  (BATCH*DIM) // 4096 columns of the reorganized matrices

// Scratch (allocation-free: __device__ globals)
// T[i][b*32+q]  = (x3[b,i,:] @ W_neigh)[q]
// S[j][b*32+q]  = (x3[b,j,:] @ W_self )[q]
__device__ float g_T[(size_t)NNODE * COLS];
__device__ float g_S[(size_t)NNODE * COLS];

// ---------------------------------------------------------------------------
// Kernel 1: per-row 32x32 matvecs. 8 rows per 256-thread block.
// Reads x once (64 MB), writes T and S (128 MB). Memory-bound, ~trivial.
// ---------------------------------------------------------------------------
__global__ __launch_bounds__(256) void prep_kernel(
    const float* __restrict__ x,      // [B, N*32]
    const float* __restrict__ Wn,     // [32,32]
    const float* __restrict__ Ws)     // [32,32]
{
    __shared__ float sWn[32 * 32];
    __shared__ float sWs[32 * 32];
    __shared__ float sx[8][32];

    int tid = threadIdx.x;
    for (int k = tid; k < 1024; k += 256) {
        sWn[k] = Wn[k];
        sWs[k] = Ws[k];
    }

    int rowBase = blockIdx.x * 8;          // global row r = b*N + i
    {
        int lr = tid >> 5, p = tid & 31;
        sx[lr][p] = x[(size_t)(rowBase + lr) * 32 + p];
    }
    __syncthreads();

    int lr = tid >> 5;
    int q  = tid & 31;
    float an = 0.f, as = 0.f;
#pragma unroll
    for (int p = 0; p < 32; ++p) {
        float xv = sx[lr][p];
        an = fmaf(xv, sWn[p * 32 + q], an);
        as = fmaf(xv, sWs[p * 32 + q], as);
    }
    int r = rowBase + lr;
    int b = r >> 12;        // r / 4096
    int i = r & 4095;       // r % 4096
    int col = (b << 5) | q;
    g_T[(size_t)i * COLS + col] = an;
    g_S[(size_t)i * COLS + col] = as;
}

// ---------------------------------------------------------------------------
// Kernel 2: C[j,c] = sum_i adj[i,j] * T[i,c]; out = relu(C + S), scattered to
// out[b, j*32+q] with c = b*32+q.
// 128x128 tile, BK=16, 256 threads, 8x8 register blocking.
// Both operands are K-major with contiguous free dim -> coalesced float4 loads.
// ---------------------------------------------------------------------------
#define BM 128
#define BN 128
#define BK 16
#define TM 8
#define TN 8

__global__ __launch_bounds__(256, 2) void gemm_kernel(
    const float* __restrict__ A,   // adj, [K=4096][M=4096], j contiguous
    float* __restrict__ out)       // [B][N][32] fp32
{
    __shared__ float As[BK][BM];
    __shared__ float Bs[BK][BN];

    int tid   = threadIdx.x;
    int mTile = blockIdx.y * BM;   // j
    int nTile = blockIdx.x * BN;   // c

    int lrow = tid >> 5;           // 0..7 (k-row within tile, +8 for second)
    int lcol = (tid & 31) * 4;     // 0..124

    int tx = tid & 15;             // column group (c)
    int ty = tid >> 4;             // row group (j)

    float acc[TM][TN] = {};

    const float* __restrict__ Bp = g_T;

    for (int k0 = 0; k0 < NNODE; k0 += BK) {
#pragma unroll
        for (int s = 0; s < 2; ++s) {
            int kr = lrow + s * 8;
            float4 av = *(const float4*)&A [(size_t)(k0 + kr) * NNODE + mTile + lcol];
            float4 bv = *(const float4*)&Bp[(size_t)(k0 + kr) * COLS  + nTile + lcol];
            *(float4*)&As[kr][lcol] = av;
            *(float4*)&Bs[kr][lcol] = bv;
        }
        __syncthreads();

#pragma unroll
        for (int kk = 0; kk < BK; ++kk) {
            float a[TM], b[TN];
#pragma unroll
            for (int u = 0; u < TM; ++u) a[u] = As[kk][ty * TM + u];
#pragma unroll
            for (int v = 0; v < TN; ++v) b[v] = Bs[kk][tx * TN + v];
#pragma unroll
            for (int u = 0; u < TM; ++u)
#pragma unroll
                for (int v = 0; v < TN; ++v)
                    acc[u][v] = fmaf(a[u], b[v], acc[u][v]);
        }
        __syncthreads();
    }

    // Epilogue: add self part, relu, scatter to [b][j][q] layout.
#pragma unroll
    for (int u = 0; u < TM; ++u) {
        int j = mTile + ty * TM + u;
#pragma unroll
        for (int v = 0; v < TN; ++v) {
            int c = nTile + tx * TN + v;
            float r = acc[u][v] + g_S[(size_t)j * COLS + c];
            r = fmaxf(r, 0.f);
            int b = c >> 5, q = c & 31;
            out[((size_t)b * NNODE + j) * DIM + q] = r;
        }
    }
}

// ---------------------------------------------------------------------------
extern "C" void kernel_launch(void* const* d_in, const int* in_sizes, int n_in,
                              void* d_out, int out_size)
{
    const float* x   = (const float*)d_in[0];   // [128, 4096*32]
    const float* adj = (const float*)d_in[1];   // [4096, 4096]
    const float* Wn  = (const float*)d_in[2];   // [32, 32]
    const float* Ws  = (const float*)d_in[3];   // [32, 32]
    // d_in[4] = batch_train (unused)
    float* out = (float*)d_out;

    // Kernel 1: build T and S
    prep_kernel<<<(BATCH * NNODE) / 8, 256>>>(x, Wn, Ws);

    // Kernel 2: big GEMM + epilogue
    dim3 grid(COLS / BN, NNODE / BM);
    gemm_kernel<<<grid, 256>>>(adj, out);
}

// round 3
// speedup vs baseline: 5.6948x; 5.6948x over previous
#include <cuda_runtime.h>
#include <cuda_bf16.h>
#include <cstdint>

// ---------------------------------------------------------------------------
// Problem constants
// ---------------------------------------------------------------------------
#define BATCH 128
#define NNODE 4096
#define DIM   32
#define COLS  4096           // BATCH*DIM

// GEMM tiling
#define BM 128               // j tile
#define BN 128               // c tile
#define BK 32                // i chunk (32 bf16 = 64 B per row)
#define STAGES 4
#define TILE_BYTES (BM * BK * 2)              // 8 KB per operand
#define STAGE_BYTES (2 * TILE_BYTES)          // 16 KB
#define NKITER (NNODE / BK)                   // 128

// Scratch (__device__ globals — allocation-free)
__device__ __nv_bfloat16 g_adjT[(size_t)NNODE * NNODE]; // [j][i]  K-major A
__device__ __nv_bfloat16 g_Tt[(size_t)COLS * NNODE];    // [c][i]  K-major B
__device__ float         g_S[(size_t)NNODE * COLS];     // [j][c]  fp32 self part

// ---------------------------------------------------------------------------
// Helpers (portable ISA only: cp.async / ldmatrix / mma.sync — no tcgen05)
// ---------------------------------------------------------------------------
__device__ __forceinline__ uint32_t smem_u32(const void* p) {
    uint32_t a;
    asm("{ .reg .u64 t; cvta.to.shared.u64 t, %1; cvt.u32.u64 %0, t; }"
        : "=r"(a) : "l"(p));
    return a;
}
// 64B logical rows packed 2-per-128B; XOR bits[4:6] with (row>>1)&7.
__device__ __forceinline__ uint32_t swz64(uint32_t off) {
    return off ^ (((off >> 7) & 7) << 4);
}
__device__ __forceinline__ void cp_async16(uint32_t dst, const void* src) {
    asm volatile("cp.async.cg.shared.global [%0], [%1], 16;"
                 :: "r"(dst), "l"(src) : "memory");
}
__device__ __forceinline__ void cp_commit() {
    asm volatile("cp.async.commit_group;" ::: "memory");
}
template <int N>
__device__ __forceinline__ void cp_wait() {
    asm volatile("cp.async.wait_group %0;" :: "n"(N) : "memory");
}
__device__ __forceinline__ void ldsm_x4(uint32_t& r0, uint32_t& r1,
                                        uint32_t& r2, uint32_t& r3, uint32_t a) {
    asm volatile("ldmatrix.sync.aligned.m8n8.x4.shared.b16 {%0,%1,%2,%3}, [%4];"
                 : "=r"(r0), "=r"(r1), "=r"(r2), "=r"(r3) : "r"(a));
}
__device__ __forceinline__ void mma_bf16(float& c0, float& c1, float& c2, float& c3,
                                         uint32_t a0, uint32_t a1, uint32_t a2, uint32_t a3,
                                         uint32_t b0, uint32_t b1) {
    asm volatile(
        "mma.sync.aligned.m16n8k16.row.col.f32.bf16.bf16.f32 "
        "{%0,%1,%2,%3}, {%4,%5,%6,%7}, {%8,%9}, {%0,%1,%2,%3};"
        : "+f"(c0), "+f"(c1), "+f"(c2), "+f"(c3)
        : "r"(a0), "r"(a1), "r"(a2), "r"(a3), "r"(b0), "r"(b1));
}

// ---------------------------------------------------------------------------
// Kernel 1: T^T (bf16, [c][i]) and S (fp32, [j][c]).
// ---------------------------------------------------------------------------
__global__ __launch_bounds__(256) void prep_kernel(
    const float* __restrict__ x,     // [B][N*32]
    const float* __restrict__ Wn,
    const float* __restrict__ Ws)
{
    __shared__ float sx[1024];
    __shared__ float sWn[1024], sWs[1024];
    __shared__ __nv_bfloat16 sT[1024];   // [q][i_loc]

    int b    = blockIdx.x >> 7;
    int i0   = (blockIdx.x & 127) * 32;
    int tid  = threadIdx.x;

    for (int e = tid; e < 1024; e += 256) {
        sWn[e] = Wn[e];
        sWs[e] = Ws[e];
        sx[e]  = x[(size_t)b * (NNODE * 32) + (size_t)i0 * 32 + e];
    }
    __syncthreads();

#pragma unroll
    for (int it = 0; it < 4; ++it) {
        int e  = tid + it * 256;
        int il = e >> 5, q = e & 31;
        float an = 0.f, as = 0.f;
#pragma unroll
        for (int p = 0; p < 32; ++p) {
            float xv = sx[il * 32 + p];
            an = fmaf(xv, sWn[p * 32 + q], an);
            as = fmaf(xv, sWs[p * 32 + q], as);
        }
        g_S[(size_t)(i0 + il) * COLS + b * 32 + q] = as;
        sT[q * 32 + il] = __float2bfloat16(an);
    }
    __syncthreads();

    const uint32_t* s32 = (const uint32_t*)sT;
    uint32_t* dst = (uint32_t*)g_Tt;
#pragma unroll
    for (int it = 0; it < 2; ++it) {
        int u   = tid + it * 256;       // 0..511
        int row = u >> 4, pr = u & 15;  // row = q
        dst[(size_t)(b * 32 + row) * (NNODE / 2) + (i0 >> 1) + pr] = s32[row * 16 + pr];
    }
}

// ---------------------------------------------------------------------------
// Kernel 2: adjT[j][i] = bf16(adj[i][j]).
// ---------------------------------------------------------------------------
__global__ __launch_bounds__(256) void adjT_kernel(const float* __restrict__ adj)
{
    __shared__ float sA[32][33];
    int j0 = blockIdx.x * 32, i0 = blockIdx.y * 32;
    int tid = threadIdx.x;

#pragma unroll
    for (int it = 0; it < 4; ++it) {
        int e = tid + it * 256;
        int r = e >> 5, c = e & 31;
        sA[r][c] = adj[(size_t)(i0 + r) * NNODE + j0 + c];
    }
    __syncthreads();

    uint32_t* dst = (uint32_t*)g_adjT;
#pragma unroll
    for (int it = 0; it < 2; ++it) {
        int u = tid + it * 256;
        int row = u >> 4, pr = u & 15;   // row = j-local
        uint32_t lo = __bfloat16_as_ushort(__float2bfloat16(sA[pr * 2][row]));
        uint32_t hi = __bfloat16_as_ushort(__float2bfloat16(sA[pr * 2 + 1][row]));
        dst[(size_t)(j0 + row) * (NNODE / 2) + (i0 >> 1) + pr] = lo | (hi << 16);
    }
}

// ---------------------------------------------------------------------------
// Kernel 3: HMMA GEMM. D[j,c] = sum_i adjT[j,i]*Tt[c,i]; out = relu(D + S)
// BM=128, BN=128, BK=32, 4-stage cp.async, 256 threads (8 warps, 2x4).
// Warp tile 64x32: 4 m-tiles (16) x 4 n-tiles (8).
// ---------------------------------------------------------------------------
__global__ __launch_bounds__(256, 2) void gemm_hmma_kernel(float* __restrict__ out)
{
    extern __shared__ char smem[];
    uint32_t base = (smem_u32(smem) + 1023) & ~1023u;

    int tid = threadIdx.x;
    int wid = tid >> 5, lane = tid & 31;
    int mTile = blockIdx.y * BM;
    int nTile = blockIdx.x * BN;

    int wm = (wid & 1) * 64;     // warp m offset
    int wn = (wid >> 1) * 32;    // warp n offset

    const char* aG = (const char*)g_adjT + (size_t)mTile * (NNODE * 2);
    const char* bG = (const char*)g_Tt   + (size_t)nTile * (NNODE * 2);

    // stage loader: k-iteration kk -> stage kk & 3
    auto load_stage = [&](int kk) {
        int s = kk & (STAGES - 1);
        uint32_t aT = base + s * STAGE_BYTES;
        uint32_t bT = aT + TILE_BYTES;
        const char* ag = aG + (size_t)kk * (BK * 2);
        const char* bg = bG + (size_t)kk * (BK * 2);
#pragma unroll
        for (int it = 0; it < 2; ++it) {          // 512 chunks / 256 thr
            int e = tid + it * 256;
            int r = e >> 2, c = e & 3;            // 128 rows x 4 x 16B
            cp_async16(aT + swz64(r * 64 + c * 16),
                       ag + (size_t)r * (NNODE * 2) + c * 16);
            cp_async16(bT + swz64(r * 64 + c * 16),
                       bg + (size_t)r * (NNODE * 2) + c * 16);
        }
        cp_commit();
    };

    // ldmatrix lane offsets (bytes within tile, before swizzle)
    int aRow = ((lane >> 3) & 1) * 8 + (lane & 7);   // m within 16
    int aKb  = (lane >> 4) * 16;                     // k-half bytes
    int bRow = (lane >> 4) * 8 + (lane & 7);         // n within 16
    int bKb  = ((lane >> 3) & 1) * 16;

    uint32_t aOff[4], bOff[2];
#pragma unroll
    for (int mi = 0; mi < 4; ++mi)
        aOff[mi] = (uint32_t)(wm + mi * 16 + aRow) * 64 + aKb;
#pragma unroll
    for (int np = 0; np < 2; ++np)
        bOff[np] = (uint32_t)(wn + np * 16 + bRow) * 64 + bKb;

    float acc[4][4][4];
#pragma unroll
    for (int mi = 0; mi < 4; ++mi)
#pragma unroll
        for (int ni = 0; ni < 4; ++ni)
#pragma unroll
            for (int v = 0; v < 4; ++v) acc[mi][ni][v] = 0.f;

    load_stage(0); load_stage(1); load_stage(2);

    for (int kk = 0; kk < NKITER; ++kk) {
        cp_wait<STAGES - 2>();
        __syncthreads();

        int s = kk & (STAGES - 1);
        uint32_t aT = base + s * STAGE_BYTES;
        uint32_t bT = aT + TILE_BYTES;

#pragma unroll
        for (int ks = 0; ks < 2; ++ks) {          // two k16 steps per BK=32
            uint32_t a[4][4], b[2][4];
#pragma unroll
            for (int mi = 0; mi < 4; ++mi)
                ldsm_x4(a[mi][0], a[mi][1], a[mi][2], a[mi][3],
                        aT + swz64(aOff[mi] + ks * 32));
#pragma unroll
            for (int np = 0; np < 2; ++np)
                ldsm_x4(b[np][0], b[np][1], b[np][2], b[np][3],
                        bT + swz64(bOff[np] + ks * 32));
#pragma unroll
            for (int mi = 0; mi < 4; ++mi)
#pragma unroll
                for (int ni = 0; ni < 4; ++ni)
                    mma_bf16(acc[mi][ni][0], acc[mi][ni][1],
                             acc[mi][ni][2], acc[mi][ni][3],
                             a[mi][0], a[mi][1], a[mi][2], a[mi][3],
                             b[ni >> 1][(ni & 1) * 2], b[ni >> 1][(ni & 1) * 2 + 1]);
        }
        __syncthreads();
        if (kk + 3 < NKITER) load_stage(kk + 3);
        else cp_commit();                          // keep group count uniform
    }

    // Epilogue: out[b][j][q] = relu(acc + S[j][c]),  c = nTile+..., b=c>>5,q=c&31
#pragma unroll
    for (int mi = 0; mi < 4; ++mi) {
        int j0 = mTile + wm + mi * 16 + (lane >> 2);   // rows j0 and j0+8
#pragma unroll
        for (int ni = 0; ni < 4; ++ni) {
            int c = nTile + wn + ni * 8 + (lane & 3) * 2;
            int b = c >> 5, q = c & 31;
            const float2* Sp0 = (const float2*)(g_S + (size_t)j0 * COLS + c);
            const float2* Sp1 = (const float2*)(g_S + (size_t)(j0 + 8) * COLS + c);
            float2 s0 = *Sp0, s1 = *Sp1;
            float2 o0, o1;
            o0.x = fmaxf(acc[mi][ni][0] + s0.x, 0.f);
            o0.y = fmaxf(acc[mi][ni][1] + s0.y, 0.f);
            o1.x = fmaxf(acc[mi][ni][2] + s1.x, 0.f);
            o1.y = fmaxf(acc[mi][ni][3] + s1.y, 0.f);
            *(float2*)(out + ((size_t)b * NNODE + j0) * DIM + q) = o0;
            *(float2*)(out + ((size_t)b * NNODE + j0 + 8) * DIM + q) = o1;
        }
    }
}

// ---------------------------------------------------------------------------
extern "C" void kernel_launch(void* const* d_in, const int* in_sizes, int n_in,
                              void* d_out, int out_size)
{
    const float* x   = (const float*)d_in[0];
    const float* adj = (const float*)d_in[1];
    const float* Wn  = (const float*)d_in[2];
    const float* Ws  = (const float*)d_in[3];
    float* out = (float*)d_out;

    prep_kernel<<<BATCH * (NNODE / 32), 256>>>(x, Wn, Ws);
    adjT_kernel<<<dim3(NNODE / 32, NNODE / 32), 256>>>(adj);

    static int smemSet = 0;
    int dynSmem = 1024 + STAGES * STAGE_BYTES;   // pad + 4 x 16KB
    if (!smemSet) {
        cudaFuncSetAttribute(gemm_hmma_kernel,
                             cudaFuncAttributeMaxDynamicSharedMemorySize, dynSmem);
        smemSet = 1;
    }
    dim3 grid(COLS / BN, NNODE / BM);
    gemm_hmma_kernel<<<grid, 256, dynSmem>>>(out);
}